// round 7
// baseline (speedup 1.0000x reference)
#include <cuda_runtime.h>
#include <cstdint>

#define FULLMASK 0xFFFFFFFFu

static constexpr int B_ = 8, C_ = 64, H_ = 512, W_ = 512, NSEG = 512;
static constexpr int WARPS = 8, THREADS = 256, CPW = 2;   // channels per warp
static constexpr int CGROUPS = C_ / (WARPS * CPW);        // 4 channel groups
static constexpr int SPLITS = 27, ROWS = 19;              // 27*19=513 >= 510 interior rows
static constexpr size_t PLANE = (size_t)H_ * W_;

__device__ __forceinline__ unsigned fmap(float f) {
    // order-preserving fp32 -> uint32 (monotone under unsigned compare)
    unsigned u = __float_as_uint(f);
    return (u & 0x80000000u) ? ~u : (u | 0x80000000u);
}

__global__ void __launch_bounds__(256) sf_init_kernel(unsigned* __restrict__ out, int n) {
    int i = blockIdx.x * blockDim.x + threadIdx.x;
    if (i < n) out[i] = 0x007FFFFFu;   // fmap(-inf)
}

__global__ void __launch_bounds__(256) sf_fini_kernel(unsigned* __restrict__ out, int n) {
    int i = blockIdx.x * blockDim.x + threadIdx.x;
    if (i < n) {
        unsigned u = out[i];
        float f = (u & 0x80000000u) ? __uint_as_float(u ^ 0x80000000u)
                                    : __uint_as_float(~u);
        if (!isfinite(f)) f = 0.0f;    // empty segments (-inf) -> 0, like reference
        out[i] = __float_as_uint(f);
    }
}

__global__ void __launch_bounds__(THREADS) sf_segmax_kernel(
    const float* __restrict__ feats,
    const int* __restrict__ mask,     // JAX x64-disabled: "int64" randint is int32
    unsigned* __restrict__ out)
{
    // 32KB bins + 2KB idx = 34KB static shared (fits default 48KB, no opt-in)
    __shared__ float bins[WARPS * CPW * NSEG];
    __shared__ int   sidx[W_];

    const int tid  = threadIdx.x;
    const int lane = tid & 31;
    const int wid  = tid >> 5;

    const int bid    = blockIdx.x;
    const int split  = bid % SPLITS;
    const int cgroup = (bid / SPLITS) % CGROUPS;
    const int b      = bid / (SPLITS * CGROUPS);

    const int r0 = 1 + split * ROWS;
    const int r1 = min(r0 + ROWS, H_ - 1);
    const int cbase = cgroup * (WARPS * CPW) + wid * CPW;

    const float NEG_INF = __int_as_float(0xff800000);

    // init warp-private bins to -inf
    for (int i = tid; i < WARPS * CPW * NSEG; i += THREADS) bins[i] = NEG_INF;

    float2* wb = (float2*)(bins + wid * CPW * NSEG);    // [NSEG] float2 (2 channels)
    const float* f0 = feats + ((size_t)(b * C_ + cbase)) * PLANE;
    const int*   mb = mask + (size_t)b * PLANE;

    __syncthreads();

    #pragma unroll 1
    for (int r = r0; r < r1; ++r) {
        // stage this row's segment ids (shared across all channels)
        const int* mrow = mb + (size_t)r * W_;
        for (int i = tid; i < W_; i += THREADS)
            sidx[i] = mrow[i] & (NSEG - 1);
        __syncthreads();

        const float* frow = f0 + (size_t)r * W_;

        #pragma unroll 1
        for (int g = 0; g < W_ / 32; ++g) {
            const int col = g * 32 + lane;
            const int seg = sidx[col];

            // intra-warp duplicate-bin detection (positions only, uniform per warp)
            unsigned peers  = __match_any_sync(FULLMASK, seg);
            int      myrank = __popc(peers & ((1u << lane) - 1u));
            int      cnt    = __popc(peers);
            int      maxcnt = __reduce_max_sync(FULLMASK, cnt);

            // 2 channel values for this position (coalesced 128B per channel)
            float v0 = __ldg(frow + col);
            float v1 = __ldg(frow + col + PLANE);
            if (col == 0 || col == W_ - 1) {            // crop cols 0 and 511
                v0 = v1 = NEG_INF;
            }

            // fold duplicate lanes into the rank-0 leader (warp-uniform loop)
            for (int k = 1; k < maxcnt; ++k) {
                bool act = (myrank == 0) && (k < cnt);
                int  s   = act ? (int)__fns(peers, 0, k + 1) : lane;
                float o0 = __shfl_sync(FULLMASK, v0, s);
                float o1 = __shfl_sync(FULLMASK, v1, s);
                if (act) {
                    v0 = fmaxf(v0, o0); v1 = fmaxf(v1, o1);
                }
            }

            // leaders do race-free non-atomic RMW into warp-private bins
            if (myrank == 0) {
                float2 cur = wb[seg];
                cur.x = fmaxf(cur.x, v0);
                cur.y = fmaxf(cur.y, v1);
                wb[seg] = cur;
            }
        }
        __syncthreads();   // protect sidx before next row's staging
    }

    // merge warp-private bins into global output via ordered-uint atomicMax
    unsigned* ob = out + ((size_t)(b * C_ + cbase)) * NSEG;
    for (int s = lane; s < NSEG; s += 32) {
        float2 v = wb[s];
        atomicMax(ob + 0 * NSEG + s, fmap(v.x));
        atomicMax(ob + 1 * NSEG + s, fmap(v.y));
    }
}

extern "C" void kernel_launch(void* const* d_in, const int* in_sizes, int n_in,
                              void* d_out, int out_size) {
    (void)in_sizes; (void)n_in;
    const float* feats = (const float*)d_in[0];
    const int*   mask  = (const int*)d_in[1];
    unsigned*    out   = (unsigned*)d_out;

    const int n = out_size;   // 8*64*512 = 262144

    sf_init_kernel<<<(n + 255) / 256, 256>>>(out, n);
    sf_segmax_kernel<<<B_ * CGROUPS * SPLITS, THREADS>>>(feats, mask, out);
    sf_fini_kernel<<<(n + 255) / 256, 256>>>(out, n);
}

// round 9
// speedup vs baseline: 3.1618x; 3.1618x over previous
#include <cuda_runtime.h>
#include <cstdint>

#define FULLMASK 0xFFFFFFFFu

static constexpr int B_ = 8, C_ = 64, H_ = 512, W_ = 512, NSEG = 512;
static constexpr int WARPS = 4, THREADS = 128, CPW = 4;   // channels per warp
static constexpr int CGROUPS = C_ / (WARPS * CPW);        // 4 channel groups
static constexpr int SPLITS = 27, ROWS = 19;              // 27*19=513 >= 510 interior rows
static constexpr size_t PLANE = (size_t)H_ * W_;

__device__ __forceinline__ unsigned fmap(float f) {
    // order-preserving fp32 -> uint32 (monotone under unsigned compare)
    unsigned u = __float_as_uint(f);
    return (u & 0x80000000u) ? ~u : (u | 0x80000000u);
}

__global__ void __launch_bounds__(256) sf_init_kernel(unsigned* __restrict__ out, int n) {
    int i = blockIdx.x * blockDim.x + threadIdx.x;
    if (i < n) out[i] = 0x007FFFFFu;   // fmap(-inf)
}

__global__ void __launch_bounds__(256) sf_fini_kernel(unsigned* __restrict__ out, int n) {
    int i = blockIdx.x * blockDim.x + threadIdx.x;
    if (i < n) {
        unsigned u = out[i];
        float f = (u & 0x80000000u) ? __uint_as_float(u ^ 0x80000000u)
                                    : __uint_as_float(~u);
        if (!isfinite(f)) f = 0.0f;    // empty segments (-inf) -> 0, like reference
        out[i] = __float_as_uint(f);
    }
}

__global__ void __launch_bounds__(THREADS) sf_segmax_kernel(
    const float* __restrict__ feats,
    const int* __restrict__ mask,     // JAX x64-disabled: "int64" randint is int32
    unsigned* __restrict__ out)
{
    // 32KB bins + 2KB packed idx/rank info = 34KB static shared
    __shared__ float bins[WARPS * CPW * NSEG];
    __shared__ int   spk[W_];   // seg(10b) | rank(5b)<<10 | maxcnt(6b)<<15

    const int tid  = threadIdx.x;
    const int lane = tid & 31;
    const int wid  = tid >> 5;

    const int bid    = blockIdx.x;
    const int split  = bid % SPLITS;
    const int cgroup = (bid / SPLITS) % CGROUPS;
    const int b      = bid / (SPLITS * CGROUPS);

    const int r0 = 1 + split * ROWS;
    const int r1 = min(r0 + ROWS, H_ - 1);
    const int cbase = cgroup * (WARPS * CPW) + wid * CPW;

    const float NEG_INF = __int_as_float(0xff800000);

    // init warp-private bins to -inf
    for (int i = tid; i < WARPS * CPW * NSEG; i += THREADS) bins[i] = NEG_INF;

    float4* wb = (float4*)(bins + wid * CPW * NSEG);    // [NSEG] float4 (4 channels)
    const float* f0 = feats + ((size_t)(b * C_ + cbase)) * PLANE;
    const int*   mb = mask + (size_t)b * PLANE;

    __syncthreads();

    #pragma unroll 1
    for (int r = r0; r < r1; ++r) {
        // ---- stage segment ids + conflict info ONCE per CTA per row ----
        // thread t handles cols t, t+128, t+256, t+384; each staging warp's
        // 32 lanes cover exactly one aligned 32-col group, identical to the
        // worker groups, so match/rank/maxcnt computed here are reusable.
        const int* mrow = mb + (size_t)r * W_;
        #pragma unroll
        for (int i = tid; i < W_; i += THREADS) {
            int seg = mrow[i] & (NSEG - 1);
            unsigned peers = __match_any_sync(FULLMASK, seg);
            int rank = __popc(peers & ((1u << lane) - 1u));
            int cnt  = __popc(peers);
            int maxc = __reduce_max_sync(FULLMASK, cnt);
            spk[i] = seg | (rank << 10) | (maxc << 15);
        }
        __syncthreads();

        const float* frow = f0 + (size_t)r * W_;

        // ---- two half-rows: batch 32 independent LDGs, then consume ----
        #pragma unroll 1
        for (int h = 0; h < 2; ++h) {
            float4 v[8];
            #pragma unroll
            for (int g = 0; g < 8; ++g) {
                int col = h * 256 + g * 32 + lane;
                v[g].x = __ldg(frow + col);
                v[g].y = __ldg(frow + col + PLANE);
                v[g].z = __ldg(frow + col + 2 * PLANE);
                v[g].w = __ldg(frow + col + 3 * PLANE);
            }
            #pragma unroll
            for (int g = 0; g < 8; ++g) {
                int col = h * 256 + g * 32 + lane;
                if (col == 0 || col == W_ - 1) {        // crop cols 0 and 511
                    v[g].x = v[g].y = v[g].z = v[g].w = NEG_INF;
                }
                int info = spk[col];
                int seg  = info & (NSEG - 1);
                int rank = (info >> 10) & 31;
                int maxc = (info >> 15) & 63;           // uniform within warp
                // rank-serialized race-free RMW: pass k writes only rank-k
                // lanes; __syncwarp() serializes passes under ITS and stops
                // the compiler from collapsing the k-loop (body is k-free).
                for (int k = 0; k < maxc; ++k) {
                    if (rank == k) {
                        float4 cur = wb[seg];
                        cur.x = fmaxf(cur.x, v[g].x);
                        cur.y = fmaxf(cur.y, v[g].y);
                        cur.z = fmaxf(cur.z, v[g].z);
                        cur.w = fmaxf(cur.w, v[g].w);
                        wb[seg] = cur;
                    }
                    __syncwarp();
                }
            }
        }
        __syncthreads();   // protect spk before next row's staging
    }

    // merge warp-private bins into global output via ordered-uint atomicMax
    unsigned* ob = out + ((size_t)(b * C_ + cbase)) * NSEG;
    for (int s = lane; s < NSEG; s += 32) {
        float4 v = wb[s];
        atomicMax(ob + 0 * NSEG + s, fmap(v.x));
        atomicMax(ob + 1 * NSEG + s, fmap(v.y));
        atomicMax(ob + 2 * NSEG + s, fmap(v.z));
        atomicMax(ob + 3 * NSEG + s, fmap(v.w));
    }
}

extern "C" void kernel_launch(void* const* d_in, const int* in_sizes, int n_in,
                              void* d_out, int out_size) {
    (void)in_sizes; (void)n_in;
    const float* feats = (const float*)d_in[0];
    const int*   mask  = (const int*)d_in[1];
    unsigned*    out   = (unsigned*)d_out;

    const int n = out_size;   // 8*64*512 = 262144

    sf_init_kernel<<<(n + 255) / 256, 256>>>(out, n);
    sf_segmax_kernel<<<B_ * CGROUPS * SPLITS, THREADS>>>(feats, mask, out);
    sf_fini_kernel<<<(n + 255) / 256, 256>>>(out, n);
}

// round 11
// speedup vs baseline: 3.7473x; 1.1852x over previous
#include <cuda_runtime.h>
#include <cstdint>

#define FULLMASK 0xFFFFFFFFu

static constexpr int B_ = 8, C_ = 64, H_ = 512, W_ = 512, NSEG = 512;
static constexpr int WARPS = 4, THREADS = 128, CPW = 4;   // channels per warp
static constexpr int CGROUPS = C_ / (WARPS * CPW);        // 4 channel groups
static constexpr int SPLITS = 27, ROWS = 19;              // 27*19=513 >= 510 interior rows
static constexpr size_t PLANE = (size_t)H_ * W_;

__device__ __forceinline__ unsigned fmap(float f) {
    // order-preserving fp32 -> uint32 (monotone under unsigned compare)
    unsigned u = __float_as_uint(f);
    return (u & 0x80000000u) ? ~u : (u | 0x80000000u);
}

__global__ void __launch_bounds__(256) sf_init_kernel(unsigned* __restrict__ out, int n) {
    int i = blockIdx.x * blockDim.x + threadIdx.x;
    if (i < n) out[i] = 0x007FFFFFu;   // fmap(-inf)
}

__global__ void __launch_bounds__(256) sf_fini_kernel(unsigned* __restrict__ out, int n) {
    int i = blockIdx.x * blockDim.x + threadIdx.x;
    if (i < n) {
        unsigned u = out[i];
        float f = (u & 0x80000000u) ? __uint_as_float(u ^ 0x80000000u)
                                    : __uint_as_float(~u);
        if (!isfinite(f)) f = 0.0f;    // empty segments (-inf) -> 0, like reference
        out[i] = __float_as_uint(f);
    }
}

__device__ __forceinline__ float f4c(const float4& v, int j) {
    // component select; j is compile-time constant after unrolling
    return j == 0 ? v.x : (j == 1 ? v.y : (j == 2 ? v.z : v.w));
}

__global__ void __launch_bounds__(THREADS) sf_segmax_kernel(
    const float* __restrict__ feats,
    const int* __restrict__ mask,     // JAX x64-disabled: "int64" randint is int32
    unsigned* __restrict__ out)
{
    // 32KB bins + 2KB packed conflict info = 34KB static shared
    __shared__ float bins[WARPS * CPW * NSEG];
    // spk[(p*4+j)*32 + lane] for strided col group {128p + 4*lane + j}
    __shared__ int   spk[W_];   // seg(10b) | rank(5b)<<10 | maxcnt(6b)<<15

    const int tid  = threadIdx.x;
    const int lane = tid & 31;
    const int wid  = tid >> 5;

    const int bid    = blockIdx.x;
    const int split  = bid % SPLITS;
    const int cgroup = (bid / SPLITS) % CGROUPS;
    const int b      = bid / (SPLITS * CGROUPS);

    const int r0 = 1 + split * ROWS;
    const int r1 = min(r0 + ROWS, H_ - 1);
    const int cbase = cgroup * (WARPS * CPW) + wid * CPW;

    const float NEG_INF = __int_as_float(0xff800000);

    // init warp-private bins to -inf
    for (int i = tid; i < WARPS * CPW * NSEG; i += THREADS) bins[i] = NEG_INF;

    float4* wb = (float4*)(bins + wid * CPW * NSEG);    // [NSEG] float4 (4 channels)
    const float* f0 = feats + ((size_t)(b * C_ + cbase)) * PLANE;
    const int*   mb = mask + (size_t)b * PLANE;

    __syncthreads();

    #pragma unroll 1
    for (int r = r0; r < r1; ++r) {
        // ---- stage conflict info: warp `wid` covers block `wid` (128 cols) ----
        // lane l holds cols 128*wid + 4l + {0,1,2,3} via one int4 LDG; for each
        // sub j, the warp's 32 lanes are exactly the strided conflict group.
        {
            const int4 m = ((const int4*)(mb + (size_t)r * W_ + 128 * wid))[lane];
            const int mj[4] = { m.x, m.y, m.z, m.w };
            #pragma unroll
            for (int j = 0; j < 4; ++j) {
                int seg = mj[j] & (NSEG - 1);
                unsigned peers = __match_any_sync(FULLMASK, seg);
                int rank = __popc(peers & ((1u << lane) - 1u));
                int cnt  = __popc(peers);
                int maxc = __reduce_max_sync(FULLMASK, cnt);
                spk[(wid * 4 + j) * 32 + lane] = seg | (rank << 10) | (maxc << 15);
            }
        }
        __syncthreads();

        const float* frow = f0 + (size_t)r * W_;

        // ---- 4 blocks of 128 cols, double-buffered LDG.128 per channel ----
        float4 cur[4], nxt[4];
        #pragma unroll
        for (int c = 0; c < 4; ++c)
            cur[c] = ((const float4*)(frow + c * PLANE))[lane];

        #pragma unroll
        for (int p = 0; p < 4; ++p) {
            if (p < 3) {
                #pragma unroll
                for (int c = 0; c < 4; ++c)
                    nxt[c] = ((const float4*)(frow + (p + 1) * 128 + c * PLANE))[lane];
            }
            #pragma unroll
            for (int j = 0; j < 4; ++j) {
                // 4-channel value vector for col = 128p + 4*lane + j
                float4 u = make_float4(f4c(cur[0], j), f4c(cur[1], j),
                                       f4c(cur[2], j), f4c(cur[3], j));
                // crop cols 0 and 511
                if ((p == 0 && j == 0 && lane == 0) ||
                    (p == 3 && j == 3 && lane == 31))
                    u = make_float4(NEG_INF, NEG_INF, NEG_INF, NEG_INF);

                int info = spk[(p * 4 + j) * 32 + lane];   // conflict-free LDS
                int seg  = info & (NSEG - 1);
                int rank = (info >> 10) & 31;
                int maxc = (info >> 15) & 63;              // warp-uniform
                // rank-serialized race-free RMW; __syncwarp() serializes
                // passes under ITS and blocks k-loop collapse.
                for (int k = 0; k < maxc; ++k) {
                    if (rank == k) {
                        float4 curb = wb[seg];
                        curb.x = fmaxf(curb.x, u.x);
                        curb.y = fmaxf(curb.y, u.y);
                        curb.z = fmaxf(curb.z, u.z);
                        curb.w = fmaxf(curb.w, u.w);
                        wb[seg] = curb;
                    }
                    __syncwarp();
                }
            }
            #pragma unroll
            for (int c = 0; c < 4; ++c) cur[c] = nxt[c];
        }
        __syncthreads();   // protect spk before next row's staging
    }

    // merge warp-private bins into global output via ordered-uint atomicMax
    unsigned* ob = out + ((size_t)(b * C_ + cbase)) * NSEG;
    for (int s = lane; s < NSEG; s += 32) {
        float4 v = wb[s];
        atomicMax(ob + 0 * NSEG + s, fmap(v.x));
        atomicMax(ob + 1 * NSEG + s, fmap(v.y));
        atomicMax(ob + 2 * NSEG + s, fmap(v.z));
        atomicMax(ob + 3 * NSEG + s, fmap(v.w));
    }
}

extern "C" void kernel_launch(void* const* d_in, const int* in_sizes, int n_in,
                              void* d_out, int out_size) {
    (void)in_sizes; (void)n_in;
    const float* feats = (const float*)d_in[0];
    const int*   mask  = (const int*)d_in[1];
    unsigned*    out   = (unsigned*)d_out;

    const int n = out_size;   // 8*64*512 = 262144

    sf_init_kernel<<<(n + 255) / 256, 256>>>(out, n);
    sf_segmax_kernel<<<B_ * CGROUPS * SPLITS, THREADS>>>(feats, mask, out);
    sf_fini_kernel<<<(n + 255) / 256, 256>>>(out, n);
}